// round 15
// baseline (speedup 1.0000x reference)
#include <cuda_runtime.h>
#include <cuda_fp16.h>
#include <cstdint>
#include <math.h>

#define NN 100000
#define NE 1600000
#define MY 64
#define MIN 256
#define NHID 64
#define NBLK 98
#define NGRP 25000   // NN/4 node groups

// ---------------- static scratch ----------------
__device__ __half2 g_h0h[NN * 32];
__device__ __half2 g_hA[NN * 32];
__device__ __half2 g_hB[NN * 32];
__device__ __half  g_w1h[NHID * MIN];
__device__ __half  g_w2h[MY * NHID];
__device__ int     g_deg[NN];
__device__ float   g_dinv[NN];
__device__ int     g_rowptr[NN + 1];
__device__ int     g_boff[NBLK + 1];
__device__ int     g_bsum[NBLK];
__device__ __align__(16) int2 g_edge[NE + 4];
__device__ unsigned g_barflag = 0;   // monotone epoch counter
__device__ unsigned g_barcnt  = 0;   // arrivals (self-cleaning)

// ---------------- graph preprocessing ----------------
__global__ void k_degcount4(const int* __restrict__ ei) {
    int e4 = blockIdx.x * blockDim.x + threadIdx.x;
    if (e4 < NE / 4) {
        int4 d = __ldg((const int4*)&ei[NE + e4 * 4]);
        atomicAdd(&g_deg[d.x], 1);
        atomicAdd(&g_deg[d.y], 1);
        atomicAdd(&g_deg[d.z], 1);
        atomicAdd(&g_deg[d.w], 1);
    }
}

__global__ void k_scan1() {
    __shared__ int wsum[32];
    int tid = threadIdx.x;
    int i = blockIdx.x * 1024 + tid;
    int v = (i < NN) ? g_deg[i] : 0;
    if (i < NN) g_dinv[i] = rsqrtf((float)(v + 1));
    int lane = tid & 31;
    int w = tid >> 5;
    int x = v;
    #pragma unroll
    for (int o = 1; o < 32; o <<= 1) {
        int t = __shfl_up_sync(0xFFFFFFFFu, x, o);
        if (lane >= o) x += t;
    }
    if (lane == 31) wsum[w] = x;
    __syncthreads();
    if (w == 0) {
        int s = wsum[lane];
        #pragma unroll
        for (int o = 1; o < 32; o <<= 1) {
            int t = __shfl_up_sync(0xFFFFFFFFu, s, o);
            if (lane >= o) s += t;
        }
        wsum[lane] = s;
    }
    __syncthreads();
    int base = (w > 0) ? wsum[w - 1] : 0;
    if (i <= NN) g_rowptr[i] = base + x - v;
    if (tid == 1023) g_bsum[blockIdx.x] = base + x;
}

__global__ void k_scan2() {
    __shared__ int s[128];
    int tid = threadIdx.x;
    int v = (tid < NBLK) ? g_bsum[tid] : 0;
    s[tid] = v;
    __syncthreads();
    #pragma unroll
    for (int o = 1; o < 128; o <<= 1) {
        int t = (tid >= o) ? s[tid - o] : 0;
        __syncthreads();
        s[tid] += t;
        __syncthreads();
    }
    if (tid < NBLK) g_boff[tid] = s[tid] - v;
    if (tid == NBLK - 1) g_boff[NBLK] = s[tid];
}

__global__ void k_scatter(const int* __restrict__ ei) {
    int e = blockIdx.x * blockDim.x + threadIdx.x;
    if (e < NE) {
        int srcv = ei[e];
        int dstv = ei[NE + e];
        int base = g_rowptr[dstv] + g_boff[dstv >> 10];
        int slot = atomicAdd(&g_deg[dstv], -1) - 1;
        float w = 0.9f * g_dinv[srcv] * g_dinv[dstv];
        g_edge[base + slot] = make_int2(srcv, __float_as_int(w));
    }
}

__global__ void k_wconv(const float* __restrict__ W1, const float* __restrict__ W2) {
    int i = blockIdx.x * 256 + threadIdx.x;
    if (i < NHID * MIN) g_w1h[i] = __float2half_rn(W1[i]);
    if (i < MY * NHID)  g_w2h[i] = __float2half_rn(W2[i]);
}

// ---------------- tensor-core MLP helpers ----------------
__device__ __forceinline__ unsigned smem_u32(const void* p) {
    return (unsigned)__cvta_generic_to_shared(p);
}

__device__ __forceinline__ void ldsm_x4(unsigned& r0, unsigned& r1, unsigned& r2, unsigned& r3,
                                        unsigned addr) {
    asm volatile("ldmatrix.sync.aligned.m8n8.x4.shared.b16 {%0,%1,%2,%3}, [%4];"
                 : "=r"(r0), "=r"(r1), "=r"(r2), "=r"(r3) : "r"(addr));
}

__device__ __forceinline__ void ldsm_x2(unsigned& r0, unsigned& r1, unsigned addr) {
    asm volatile("ldmatrix.sync.aligned.m8n8.x2.shared.b16 {%0,%1}, [%2];"
                 : "=r"(r0), "=r"(r1) : "r"(addr));
}

__device__ __forceinline__ void mma16816(float* d,
                                         unsigned a0, unsigned a1, unsigned a2, unsigned a3,
                                         unsigned b0, unsigned b1) {
    asm volatile("mma.sync.aligned.m16n8k16.row.col.f32.f16.f16.f32 "
                 "{%0,%1,%2,%3}, {%4,%5,%6,%7}, {%8,%9}, {%0,%1,%2,%3};"
                 : "+f"(d[0]), "+f"(d[1]), "+f"(d[2]), "+f"(d[3])
                 : "r"(a0), "r"(a1), "r"(a2), "r"(a3), "r"(b0), "r"(b1));
}

// ---------------- fused 2-layer MLP on tensor cores ----------------
#define XS_STR 72
__global__ void k_mlp_tc(const float* __restrict__ x,
                         const float* __restrict__ b1,
                         const float* __restrict__ b2) {
    __shared__ __align__(16) __half xs[128][XS_STR];
    __shared__ __align__(16) __half hid[128][XS_STR];
    __shared__ __align__(16) __half wbuf[64][XS_STR];

    int t = threadIdx.x;
    int w = t >> 5;
    int lane = t & 31;
    int row0 = blockIdx.x * 128;

    float acc[8][4];
    #pragma unroll
    for (int j = 0; j < 8; j++) {
        acc[j][0] = 0.f; acc[j][1] = 0.f; acc[j][2] = 0.f; acc[j][3] = 0.f;
    }

    int a_r    = 16 * w + (lane & 15);
    int a_koff = (lane < 16) ? 0 : 8;
    int b_r    = lane & 7;
    int b_koff = ((lane >> 3) & 1) ? 8 : 0;

    for (int chunk = 0; chunk < 4; chunk++) {
        int kk = chunk * 64;
        for (int i = t; i < 128 * 16; i += 256) {
            int r = i >> 4;
            int c4 = i & 15;
            int grow = row0 + r;
            float4 v = make_float4(0.f, 0.f, 0.f, 0.f);
            if (grow < NN) v = *(const float4*)&x[(size_t)grow * MIN + kk + c4 * 4];
            __half2 p0 = __floats2half2_rn(v.x, v.y);
            __half2 p1 = __floats2half2_rn(v.z, v.w);
            uint2 st;
            st.x = *(unsigned*)&p0;
            st.y = *(unsigned*)&p1;
            *(uint2*)&xs[r][c4 * 4] = st;
        }
        for (int i = t; i < 64 * 16; i += 256) {
            int r = i >> 4;
            int c4 = i & 15;
            *(uint2*)&wbuf[r][c4 * 4] = *(const uint2*)&g_w1h[r * MIN + kk + c4 * 4];
        }
        __syncthreads();
        #pragma unroll
        for (int ks = 0; ks < 4; ks++) {
            int k0 = ks * 16;
            unsigned a0, a1, a2, a3;
            ldsm_x4(a0, a1, a2, a3, smem_u32(&xs[a_r][k0 + a_koff]));
            #pragma unroll
            for (int j = 0; j < 8; j++) {
                unsigned f0, f1;
                ldsm_x2(f0, f1, smem_u32(&wbuf[8 * j + b_r][k0 + b_koff]));
                mma16816(acc[j], a0, a1, a2, a3, f0, f1);
            }
        }
        __syncthreads();
    }

    int rowA = 16 * w + (lane >> 2);
    int colb = (lane & 3) * 2;
    #pragma unroll
    for (int j = 0; j < 8; j++) {
        int col = 8 * j + colb;
        float bj0 = b1[col];
        float bj1 = b1[col + 1];
        *(__half2*)&hid[rowA][col] =
            __floats2half2_rn(fmaxf(acc[j][0] + bj0, 0.f), fmaxf(acc[j][1] + bj1, 0.f));
        *(__half2*)&hid[rowA + 8][col] =
            __floats2half2_rn(fmaxf(acc[j][2] + bj0, 0.f), fmaxf(acc[j][3] + bj1, 0.f));
    }
    for (int i = t; i < 64 * 16; i += 256) {
        int r = i >> 4;
        int c4 = i & 15;
        *(uint2*)&wbuf[r][c4 * 4] = *(const uint2*)&g_w2h[r * NHID + c4 * 4];
    }
    __syncthreads();

    float acc2[8][4];
    #pragma unroll
    for (int j = 0; j < 8; j++) {
        acc2[j][0] = 0.f; acc2[j][1] = 0.f; acc2[j][2] = 0.f; acc2[j][3] = 0.f;
    }
    #pragma unroll
    for (int ks = 0; ks < 4; ks++) {
        int k0 = ks * 16;
        unsigned a0, a1, a2, a3;
        ldsm_x4(a0, a1, a2, a3, smem_u32(&hid[a_r][k0 + a_koff]));
        #pragma unroll
        for (int j = 0; j < 8; j++) {
            unsigned f0, f1;
            ldsm_x2(f0, f1, smem_u32(&wbuf[8 * j + b_r][k0 + b_koff]));
            mma16816(acc2[j], a0, a1, a2, a3, f0, f1);
        }
    }

    int r0g = row0 + rowA;
    int r1g = r0g + 8;
    #pragma unroll
    for (int j = 0; j < 8; j++) {
        int col = 8 * j + colb;
        float bj0 = b2[col];
        float bj1 = b2[col + 1];
        if (r0g < NN) {
            __half2 h2 = __floats2half2_rn(acc2[j][0] + bj0, acc2[j][1] + bj1);
            g_h0h[r0g * 32 + col / 2] = h2;
            g_hA[r0g * 32 + col / 2]  = h2;
        }
        if (r1g < NN) {
            __half2 h2 = __floats2half2_rn(acc2[j][2] + bj0, acc2[j][3] + bj1);
            g_h0h[r1g * 32 + col / 2] = h2;
            g_hA[r1g * 32 + col / 2]  = h2;
        }
    }
}

// ---------------- per-node propagation body ----------------
// mode: 0 = first iter (hin==h0), 1 = middle, 2 = last (fp32 out)
__device__ __forceinline__ void prop_node(int n, int lane, int mode,
                                          const __half2* __restrict__ hin,
                                          __half2* __restrict__ hout,
                                          float2* __restrict__ outf) {
    int start = g_rowptr[n]     + g_boff[n >> 10];
    int end   = g_rowptr[n + 1] + g_boff[(n + 1) >> 10];
    float dn = g_dinv[n];
    int idx = n * 32 + lane;
    float2 hv = __half22float2(__ldg(&hin[idx]));
    float sl = 0.9f * dn * dn;
    float ax0, ay0;
    if (mode == 0) {
        float c = sl + 0.1f;
        ax0 = c * hv.x;
        ay0 = c * hv.y;
    } else {
        float2 t0 = __half22float2(__ldg(&g_h0h[idx]));
        ax0 = fmaf(sl, hv.x, 0.1f * t0.x);
        ay0 = fmaf(sl, hv.y, 0.1f * t0.y);
    }
    float ax1 = 0.f, ay1 = 0.f, ax2 = 0.f, ay2 = 0.f, ax3 = 0.f, ay3 = 0.f;

    int p = start;
    if ((p & 1) && p < end) {
        int2 e = __ldg(&g_edge[p]);
        float w = __int_as_float(e.y);
        float2 v = __half22float2(__ldg(&hin[e.x * 32 + lane]));
        ax0 = fmaf(w, v.x, ax0); ay0 = fmaf(w, v.y, ay0);
        p++;
    }
    for (; p + 8 <= end; p += 8) {
        int4 e01 = __ldg((const int4*)&g_edge[p]);
        int4 e23 = __ldg((const int4*)&g_edge[p + 2]);
        int4 e45 = __ldg((const int4*)&g_edge[p + 4]);
        int4 e67 = __ldg((const int4*)&g_edge[p + 6]);
        float2 v0 = __half22float2(__ldg(&hin[e01.x * 32 + lane]));
        float2 v1 = __half22float2(__ldg(&hin[e01.z * 32 + lane]));
        float2 v2 = __half22float2(__ldg(&hin[e23.x * 32 + lane]));
        float2 v3 = __half22float2(__ldg(&hin[e23.z * 32 + lane]));
        float2 v4 = __half22float2(__ldg(&hin[e45.x * 32 + lane]));
        float2 v5 = __half22float2(__ldg(&hin[e45.z * 32 + lane]));
        float2 v6 = __half22float2(__ldg(&hin[e67.x * 32 + lane]));
        float2 v7 = __half22float2(__ldg(&hin[e67.z * 32 + lane]));
        float w0 = __int_as_float(e01.y);
        float w1 = __int_as_float(e01.w);
        float w2 = __int_as_float(e23.y);
        float w3 = __int_as_float(e23.w);
        float w4 = __int_as_float(e45.y);
        float w5 = __int_as_float(e45.w);
        float w6 = __int_as_float(e67.y);
        float w7 = __int_as_float(e67.w);
        ax0 = fmaf(w0, v0.x, ax0); ay0 = fmaf(w0, v0.y, ay0);
        ax1 = fmaf(w1, v1.x, ax1); ay1 = fmaf(w1, v1.y, ay1);
        ax2 = fmaf(w2, v2.x, ax2); ay2 = fmaf(w2, v2.y, ay2);
        ax3 = fmaf(w3, v3.x, ax3); ay3 = fmaf(w3, v3.y, ay3);
        ax0 = fmaf(w4, v4.x, ax0); ay0 = fmaf(w4, v4.y, ay0);
        ax1 = fmaf(w5, v5.x, ax1); ay1 = fmaf(w5, v5.y, ay1);
        ax2 = fmaf(w6, v6.x, ax2); ay2 = fmaf(w6, v6.y, ay2);
        ax3 = fmaf(w7, v7.x, ax3); ay3 = fmaf(w7, v7.y, ay3);
    }
    if (p + 4 <= end) {
        int4 e01 = __ldg((const int4*)&g_edge[p]);
        int4 e23 = __ldg((const int4*)&g_edge[p + 2]);
        float2 v0 = __half22float2(__ldg(&hin[e01.x * 32 + lane]));
        float2 v1 = __half22float2(__ldg(&hin[e01.z * 32 + lane]));
        float2 v2 = __half22float2(__ldg(&hin[e23.x * 32 + lane]));
        float2 v3 = __half22float2(__ldg(&hin[e23.z * 32 + lane]));
        float w0 = __int_as_float(e01.y);
        float w1 = __int_as_float(e01.w);
        float w2 = __int_as_float(e23.y);
        float w3 = __int_as_float(e23.w);
        ax0 = fmaf(w0, v0.x, ax0); ay0 = fmaf(w0, v0.y, ay0);
        ax1 = fmaf(w1, v1.x, ax1); ay1 = fmaf(w1, v1.y, ay1);
        ax2 = fmaf(w2, v2.x, ax2); ay2 = fmaf(w2, v2.y, ay2);
        ax3 = fmaf(w3, v3.x, ax3); ay3 = fmaf(w3, v3.y, ay3);
        p += 4;
    }
    if (p + 2 <= end) {
        int4 e01 = __ldg((const int4*)&g_edge[p]);
        float w0 = __int_as_float(e01.y);
        float w1 = __int_as_float(e01.w);
        float2 v0 = __half22float2(__ldg(&hin[e01.x * 32 + lane]));
        float2 v1 = __half22float2(__ldg(&hin[e01.z * 32 + lane]));
        ax1 = fmaf(w0, v0.x, ax1); ay1 = fmaf(w0, v0.y, ay1);
        ax2 = fmaf(w1, v1.x, ax2); ay2 = fmaf(w1, v1.y, ay2);
        p += 2;
    }
    if (p < end) {
        int2 e = __ldg(&g_edge[p]);
        float w = __int_as_float(e.y);
        float2 v = __half22float2(__ldg(&hin[e.x * 32 + lane]));
        ax3 = fmaf(w, v.x, ax3); ay3 = fmaf(w, v.y, ay3);
    }
    float ox = (ax0 + ax1) + (ax2 + ax3);
    float oy = (ay0 + ay1) + (ay2 + ay3);
    if (mode == 2) {
        float2 o;
        o.x = ox;
        o.y = oy;
        outf[idx] = o;
    } else {
        hout[idx] = __floats2half2_rn(ox, oy);
    }
}

// ---------------- persistent kernel: all 10 iterations, software grid barrier ----------------
__global__ void __launch_bounds__(128) k_prop_all(float2* __restrict__ outf) {
    __shared__ unsigned sbase;
    if (threadIdx.x == 0 && threadIdx.y == 0)
        sbase = *(volatile unsigned*)&g_barflag;   // stable: no block has arrived yet
    __syncthreads();
    unsigned base = sbase;
    int lane = threadIdx.x;
    int nb = gridDim.x;

    for (int k = 0; k < 10; k++) {
        const __half2* hin = (k & 1) ? g_hB : g_hA;
        __half2* hout      = (k & 1) ? g_hA : g_hB;
        int mode = (k == 0) ? 0 : ((k == 9) ? 2 : 1);
        for (int grp = blockIdx.x; grp < NGRP; grp += nb) {
            int n = grp * 4 + threadIdx.y;
            prop_node(n, lane, mode, hin, hout, outf);   // NN divisible by 4
        }
        if (k < 9) {
            // software grid barrier, epoch = base + k + 1
            __syncthreads();
            if (threadIdx.x == 0 && threadIdx.y == 0) {
                __threadfence();
                unsigned v = atomicAdd(&g_barcnt, 1);
                unsigned target = base + (unsigned)(k + 1);
                if (v == (unsigned)nb - 1) {
                    g_barcnt = 0;
                    __threadfence();
                    *(volatile unsigned*)&g_barflag = target;
                } else {
                    while (*(volatile unsigned*)&g_barflag != target) { }
                }
                __threadfence();
            }
            __syncthreads();
        }
    }
}

// ---------------- launch ----------------
extern "C" void kernel_launch(void* const* d_in, const int* in_sizes, int n_in,
                              void* d_out, int out_size) {
    const float* x  = nullptr;
    const float* W1 = nullptr;
    const float* b1 = nullptr;
    const float* W2 = nullptr;
    const float* b2 = nullptr;
    const int*   ei = nullptr;
    for (int i = 0; i < n_in; i++) {
        int s = in_sizes[i];
        if      (s == NN * MIN)   x  = (const float*)d_in[i];
        else if (s == NHID * MIN) W1 = (const float*)d_in[i];
        else if (s == MY * NHID)  W2 = (const float*)d_in[i];
        else if (s == 2 * NE)     ei = (const int*)d_in[i];
        else if (s == NHID) {
            if (!b1) b1 = (const float*)d_in[i];
            else     b2 = (const float*)d_in[i];
        }
    }

    static cudaStream_t s2 = nullptr;
    static cudaEvent_t evFork = nullptr, evJoin = nullptr;
    static int nblocks = 0;
    if (s2 == nullptr) {
        cudaStreamCreateWithFlags(&s2, cudaStreamNonBlocking);
        cudaEventCreateWithFlags(&evFork, cudaEventDisableTiming);
        cudaEventCreateWithFlags(&evJoin, cudaEventDisableTiming);
        int perSM = 0;
        cudaOccupancyMaxActiveBlocksPerMultiprocessor(&perSM, k_prop_all, 128, 0);
        int nsm = 0;
        int dev = 0;
        cudaGetDevice(&dev);
        cudaDeviceGetAttribute(&nsm, cudaDevAttrMultiProcessorCount, dev);
        nblocks = perSM * nsm;
        if (nblocks > NGRP) nblocks = NGRP;
        if (nblocks < 1) nblocks = 1;
    }

    cudaEventRecord(evFork, 0);
    cudaStreamWaitEvent(s2, evFork, 0);

    k_wconv<<<(NHID * MIN + 255) / 256, 256, 0, s2>>>(W1, W2);
    k_mlp_tc<<<(NN + 127) / 128, 256, 0, s2>>>(x, b1, b2);
    cudaEventRecord(evJoin, s2);

    k_degcount4<<<(NE / 4 + 255) / 256, 256>>>(ei);
    k_scan1<<<NBLK, 1024>>>();
    k_scan2<<<1, 128>>>();
    k_scatter<<<(NE + 255) / 256, 256>>>(ei);

    cudaStreamWaitEvent(0, evJoin, 0);

    dim3 pb(32, 4);
    k_prop_all<<<nblocks, pb>>>((float2*)d_out);
}

// round 16
// speedup vs baseline: 1.2791x; 1.2791x over previous
#include <cuda_runtime.h>
#include <cuda_fp16.h>
#include <cstdint>
#include <math.h>

#define NN 100000
#define NE 1600000
#define MY 64
#define MIN 256
#define NHID 64
#define NBLK 98

// ---------------- static scratch ----------------
__device__ __half2 g_h0h[NN * 32];      // teleport term, fp16
__device__ __half2 g_hA[NN * 32];       // ping
__device__ __half2 g_hB[NN * 32];       // pong
__device__ __half  g_w1h[NHID * MIN];   // fp16 W1
__device__ __half  g_w2h[MY * NHID];    // fp16 W2
__device__ int     g_deg[NN];           // degree; self-cleaning (scatter drains to 0)
__device__ float   g_dinv[NN];
__device__ int     g_rowptr[NN + 1];    // BLOCK-LOCAL exclusive scan
__device__ int     g_boff[NBLK + 1];    // block offsets (global = rowptr + boff[i>>10])
__device__ int     g_bsum[NBLK];
__device__ __align__(16) int2 g_edge[NE + 4];

// ---------------- graph preprocessing ----------------
__global__ void k_degcount4(const int* __restrict__ ei) {
    int e4 = blockIdx.x * blockDim.x + threadIdx.x;
    if (e4 < NE / 4) {
        int4 d = __ldg((const int4*)&ei[NE + e4 * 4]);
        atomicAdd(&g_deg[d.x], 1);
        atomicAdd(&g_deg[d.y], 1);
        atomicAdd(&g_deg[d.z], 1);
        atomicAdd(&g_deg[d.w], 1);
    }
}

__global__ void k_scan1() {
    __shared__ int wsum[32];
    int tid = threadIdx.x;
    int i = blockIdx.x * 1024 + tid;
    int v = (i < NN) ? g_deg[i] : 0;
    if (i < NN) g_dinv[i] = rsqrtf((float)(v + 1));
    int lane = tid & 31;
    int w = tid >> 5;
    int x = v;
    #pragma unroll
    for (int o = 1; o < 32; o <<= 1) {
        int t = __shfl_up_sync(0xFFFFFFFFu, x, o);
        if (lane >= o) x += t;
    }
    if (lane == 31) wsum[w] = x;
    __syncthreads();
    if (w == 0) {
        int s = wsum[lane];
        #pragma unroll
        for (int o = 1; o < 32; o <<= 1) {
            int t = __shfl_up_sync(0xFFFFFFFFu, s, o);
            if (lane >= o) s += t;
        }
        wsum[lane] = s;
    }
    __syncthreads();
    int base = (w > 0) ? wsum[w - 1] : 0;
    if (i <= NN) g_rowptr[i] = base + x - v;
    if (tid == 1023) g_bsum[blockIdx.x] = base + x;
}

__global__ void k_scan2() {
    __shared__ int s[128];
    int tid = threadIdx.x;
    int v = (tid < NBLK) ? g_bsum[tid] : 0;
    s[tid] = v;
    __syncthreads();
    #pragma unroll
    for (int o = 1; o < 128; o <<= 1) {
        int t = (tid >= o) ? s[tid - o] : 0;
        __syncthreads();
        s[tid] += t;
        __syncthreads();
    }
    if (tid < NBLK) g_boff[tid] = s[tid] - v;
    if (tid == NBLK - 1) g_boff[NBLK] = s[tid];
}

__global__ void k_scatter(const int* __restrict__ ei) {
    int e = blockIdx.x * blockDim.x + threadIdx.x;
    if (e < NE) {
        int srcv = ei[e];
        int dstv = ei[NE + e];
        int base = g_rowptr[dstv] + g_boff[dstv >> 10];
        int slot = atomicAdd(&g_deg[dstv], -1) - 1;
        float w = 0.9f * g_dinv[srcv] * g_dinv[dstv];
        g_edge[base + slot] = make_int2(srcv, __float_as_int(w));
    }
}

__global__ void k_wconv(const float* __restrict__ W1, const float* __restrict__ W2) {
    int i = blockIdx.x * 256 + threadIdx.x;
    if (i < NHID * MIN) g_w1h[i] = __float2half_rn(W1[i]);
    if (i < MY * NHID)  g_w2h[i] = __float2half_rn(W2[i]);
}

// ---------------- tensor-core MLP helpers ----------------
__device__ __forceinline__ unsigned smem_u32(const void* p) {
    return (unsigned)__cvta_generic_to_shared(p);
}

__device__ __forceinline__ void ldsm_x4(unsigned& r0, unsigned& r1, unsigned& r2, unsigned& r3,
                                        unsigned addr) {
    asm volatile("ldmatrix.sync.aligned.m8n8.x4.shared.b16 {%0,%1,%2,%3}, [%4];"
                 : "=r"(r0), "=r"(r1), "=r"(r2), "=r"(r3) : "r"(addr));
}

__device__ __forceinline__ void ldsm_x2(unsigned& r0, unsigned& r1, unsigned addr) {
    asm volatile("ldmatrix.sync.aligned.m8n8.x2.shared.b16 {%0,%1}, [%2];"
                 : "=r"(r0), "=r"(r1) : "r"(addr));
}

__device__ __forceinline__ void mma16816(float* d,
                                         unsigned a0, unsigned a1, unsigned a2, unsigned a3,
                                         unsigned b0, unsigned b1) {
    asm volatile("mma.sync.aligned.m16n8k16.row.col.f32.f16.f16.f32 "
                 "{%0,%1,%2,%3}, {%4,%5,%6,%7}, {%8,%9}, {%0,%1,%2,%3};"
                 : "+f"(d[0]), "+f"(d[1]), "+f"(d[2]), "+f"(d[3])
                 : "r"(a0), "r"(a1), "r"(a2), "r"(a3), "r"(b0), "r"(b1));
}

// ---------------- fused 2-layer MLP on tensor cores ----------------
#define XS_STR 72
__global__ void k_mlp_tc(const float* __restrict__ x,
                         const float* __restrict__ b1,
                         const float* __restrict__ b2) {
    __shared__ __align__(16) __half xs[128][XS_STR];
    __shared__ __align__(16) __half hid[128][XS_STR];
    __shared__ __align__(16) __half wbuf[64][XS_STR];

    int t = threadIdx.x;
    int w = t >> 5;
    int lane = t & 31;
    int row0 = blockIdx.x * 128;

    float acc[8][4];
    #pragma unroll
    for (int j = 0; j < 8; j++) {
        acc[j][0] = 0.f; acc[j][1] = 0.f; acc[j][2] = 0.f; acc[j][3] = 0.f;
    }

    int a_r    = 16 * w + (lane & 15);
    int a_koff = (lane < 16) ? 0 : 8;
    int b_r    = lane & 7;
    int b_koff = ((lane >> 3) & 1) ? 8 : 0;

    for (int chunk = 0; chunk < 4; chunk++) {
        int kk = chunk * 64;
        for (int i = t; i < 128 * 16; i += 256) {
            int r = i >> 4;
            int c4 = i & 15;
            int grow = row0 + r;
            float4 v = make_float4(0.f, 0.f, 0.f, 0.f);
            if (grow < NN) v = *(const float4*)&x[(size_t)grow * MIN + kk + c4 * 4];
            __half2 p0 = __floats2half2_rn(v.x, v.y);
            __half2 p1 = __floats2half2_rn(v.z, v.w);
            uint2 st;
            st.x = *(unsigned*)&p0;
            st.y = *(unsigned*)&p1;
            *(uint2*)&xs[r][c4 * 4] = st;
        }
        for (int i = t; i < 64 * 16; i += 256) {
            int r = i >> 4;
            int c4 = i & 15;
            *(uint2*)&wbuf[r][c4 * 4] = *(const uint2*)&g_w1h[r * MIN + kk + c4 * 4];
        }
        __syncthreads();
        #pragma unroll
        for (int ks = 0; ks < 4; ks++) {
            int k0 = ks * 16;
            unsigned a0, a1, a2, a3;
            ldsm_x4(a0, a1, a2, a3, smem_u32(&xs[a_r][k0 + a_koff]));
            #pragma unroll
            for (int j = 0; j < 8; j++) {
                unsigned f0, f1;
                ldsm_x2(f0, f1, smem_u32(&wbuf[8 * j + b_r][k0 + b_koff]));
                mma16816(acc[j], a0, a1, a2, a3, f0, f1);
            }
        }
        __syncthreads();
    }

    int rowA = 16 * w + (lane >> 2);
    int colb = (lane & 3) * 2;
    #pragma unroll
    for (int j = 0; j < 8; j++) {
        int col = 8 * j + colb;
        float bj0 = b1[col];
        float bj1 = b1[col + 1];
        *(__half2*)&hid[rowA][col] =
            __floats2half2_rn(fmaxf(acc[j][0] + bj0, 0.f), fmaxf(acc[j][1] + bj1, 0.f));
        *(__half2*)&hid[rowA + 8][col] =
            __floats2half2_rn(fmaxf(acc[j][2] + bj0, 0.f), fmaxf(acc[j][3] + bj1, 0.f));
    }
    for (int i = t; i < 64 * 16; i += 256) {
        int r = i >> 4;
        int c4 = i & 15;
        *(uint2*)&wbuf[r][c4 * 4] = *(const uint2*)&g_w2h[r * NHID + c4 * 4];
    }
    __syncthreads();

    float acc2[8][4];
    #pragma unroll
    for (int j = 0; j < 8; j++) {
        acc2[j][0] = 0.f; acc2[j][1] = 0.f; acc2[j][2] = 0.f; acc2[j][3] = 0.f;
    }
    #pragma unroll
    for (int ks = 0; ks < 4; ks++) {
        int k0 = ks * 16;
        unsigned a0, a1, a2, a3;
        ldsm_x4(a0, a1, a2, a3, smem_u32(&hid[a_r][k0 + a_koff]));
        #pragma unroll
        for (int j = 0; j < 8; j++) {
            unsigned f0, f1;
            ldsm_x2(f0, f1, smem_u32(&wbuf[8 * j + b_r][k0 + b_koff]));
            mma16816(acc2[j], a0, a1, a2, a3, f0, f1);
        }
    }

    int r0g = row0 + rowA;
    int r1g = r0g + 8;
    #pragma unroll
    for (int j = 0; j < 8; j++) {
        int col = 8 * j + colb;
        float bj0 = b2[col];
        float bj1 = b2[col + 1];
        if (r0g < NN) {
            __half2 h2 = __floats2half2_rn(acc2[j][0] + bj0, acc2[j][1] + bj1);
            g_h0h[r0g * 32 + col / 2] = h2;
            g_hA[r0g * 32 + col / 2]  = h2;
        }
        if (r1g < NN) {
            __half2 h2 = __floats2half2_rn(acc2[j][2] + bj0, acc2[j][3] + bj1);
            g_h0h[r1g * 32 + col / 2] = h2;
            g_hA[r1g * 32 + col / 2]  = h2;
        }
    }
}

// ---------------- APPNP propagation step ----------------
// MODE: 0 = first iter (hin == h0), 1 = middle, 2 = last (fp32 output)
// block = (32 lanes, 2 nodes)
template <int MODE>
__global__ void k_prop(const __half2* __restrict__ hin, __half2* __restrict__ hout,
                       const __half2* __restrict__ h0h, float2* __restrict__ outf) {
    int n = blockIdx.x * 2 + threadIdx.y;
    if (n >= NN) return;
    int lane = threadIdx.x;
    int start = g_rowptr[n]     + g_boff[n >> 10];
    int end   = g_rowptr[n + 1] + g_boff[(n + 1) >> 10];
    float dn = g_dinv[n];
    int idx = n * 32 + lane;
    float2 hv = __half22float2(__ldg(&hin[idx]));
    float sl = 0.9f * dn * dn;
    float ax0, ay0;
    if (MODE == 0) {
        float c = sl + 0.1f;
        ax0 = c * hv.x;
        ay0 = c * hv.y;
    } else {
        float2 t0 = __half22float2(__ldg(&h0h[idx]));
        ax0 = fmaf(sl, hv.x, 0.1f * t0.x);
        ay0 = fmaf(sl, hv.y, 0.1f * t0.y);
    }
    float ax1 = 0.f, ay1 = 0.f, ax2 = 0.f, ay2 = 0.f, ax3 = 0.f, ay3 = 0.f;

    int p = start;
    if ((p & 1) && p < end) {
        int2 e = __ldg(&g_edge[p]);
        float w = __int_as_float(e.y);
        float2 v = __half22float2(__ldg(&hin[e.x * 32 + lane]));
        ax0 = fmaf(w, v.x, ax0); ay0 = fmaf(w, v.y, ay0);
        p++;
    }
    for (; p + 8 <= end; p += 8) {
        int4 e01 = __ldg((const int4*)&g_edge[p]);
        int4 e23 = __ldg((const int4*)&g_edge[p + 2]);
        int4 e45 = __ldg((const int4*)&g_edge[p + 4]);
        int4 e67 = __ldg((const int4*)&g_edge[p + 6]);
        float2 v0 = __half22float2(__ldg(&hin[e01.x * 32 + lane]));
        float2 v1 = __half22float2(__ldg(&hin[e01.z * 32 + lane]));
        float2 v2 = __half22float2(__ldg(&hin[e23.x * 32 + lane]));
        float2 v3 = __half22float2(__ldg(&hin[e23.z * 32 + lane]));
        float2 v4 = __half22float2(__ldg(&hin[e45.x * 32 + lane]));
        float2 v5 = __half22float2(__ldg(&hin[e45.z * 32 + lane]));
        float2 v6 = __half22float2(__ldg(&hin[e67.x * 32 + lane]));
        float2 v7 = __half22float2(__ldg(&hin[e67.z * 32 + lane]));
        float w0 = __int_as_float(e01.y);
        float w1 = __int_as_float(e01.w);
        float w2 = __int_as_float(e23.y);
        float w3 = __int_as_float(e23.w);
        float w4 = __int_as_float(e45.y);
        float w5 = __int_as_float(e45.w);
        float w6 = __int_as_float(e67.y);
        float w7 = __int_as_float(e67.w);
        ax0 = fmaf(w0, v0.x, ax0); ay0 = fmaf(w0, v0.y, ay0);
        ax1 = fmaf(w1, v1.x, ax1); ay1 = fmaf(w1, v1.y, ay1);
        ax2 = fmaf(w2, v2.x, ax2); ay2 = fmaf(w2, v2.y, ay2);
        ax3 = fmaf(w3, v3.x, ax3); ay3 = fmaf(w3, v3.y, ay3);
        ax0 = fmaf(w4, v4.x, ax0); ay0 = fmaf(w4, v4.y, ay0);
        ax1 = fmaf(w5, v5.x, ax1); ay1 = fmaf(w5, v5.y, ay1);
        ax2 = fmaf(w6, v6.x, ax2); ay2 = fmaf(w6, v6.y, ay2);
        ax3 = fmaf(w7, v7.x, ax3); ay3 = fmaf(w7, v7.y, ay3);
    }
    if (p + 4 <= end) {
        int4 e01 = __ldg((const int4*)&g_edge[p]);
        int4 e23 = __ldg((const int4*)&g_edge[p + 2]);
        float2 v0 = __half22float2(__ldg(&hin[e01.x * 32 + lane]));
        float2 v1 = __half22float2(__ldg(&hin[e01.z * 32 + lane]));
        float2 v2 = __half22float2(__ldg(&hin[e23.x * 32 + lane]));
        float2 v3 = __half22float2(__ldg(&hin[e23.z * 32 + lane]));
        float w0 = __int_as_float(e01.y);
        float w1 = __int_as_float(e01.w);
        float w2 = __int_as_float(e23.y);
        float w3 = __int_as_float(e23.w);
        ax0 = fmaf(w0, v0.x, ax0); ay0 = fmaf(w0, v0.y, ay0);
        ax1 = fmaf(w1, v1.x, ax1); ay1 = fmaf(w1, v1.y, ay1);
        ax2 = fmaf(w2, v2.x, ax2); ay2 = fmaf(w2, v2.y, ay2);
        ax3 = fmaf(w3, v3.x, ax3); ay3 = fmaf(w3, v3.y, ay3);
        p += 4;
    }
    if (p + 2 <= end) {
        int4 e01 = __ldg((const int4*)&g_edge[p]);
        float w0 = __int_as_float(e01.y);
        float w1 = __int_as_float(e01.w);
        float2 v0 = __half22float2(__ldg(&hin[e01.x * 32 + lane]));
        float2 v1 = __half22float2(__ldg(&hin[e01.z * 32 + lane]));
        ax1 = fmaf(w0, v0.x, ax1); ay1 = fmaf(w0, v0.y, ay1);
        ax2 = fmaf(w1, v1.x, ax2); ay2 = fmaf(w1, v1.y, ay2);
        p += 2;
    }
    if (p < end) {
        int2 e = __ldg(&g_edge[p]);
        float w = __int_as_float(e.y);
        float2 v = __half22float2(__ldg(&hin[e.x * 32 + lane]));
        ax3 = fmaf(w, v.x, ax3); ay3 = fmaf(w, v.y, ay3);
    }
    float ox = (ax0 + ax1) + (ax2 + ax3);
    float oy = (ay0 + ay1) + (ay2 + ay3);
    if (MODE == 2) {
        float2 o;
        o.x = ox;
        o.y = oy;
        outf[idx] = o;
    } else {
        hout[idx] = __floats2half2_rn(ox, oy);
    }
}

// ---------------- launch ----------------
extern "C" void kernel_launch(void* const* d_in, const int* in_sizes, int n_in,
                              void* d_out, int out_size) {
    const float* x  = nullptr;
    const float* W1 = nullptr;
    const float* b1 = nullptr;
    const float* W2 = nullptr;
    const float* b2 = nullptr;
    const int*   ei = nullptr;
    for (int i = 0; i < n_in; i++) {
        int s = in_sizes[i];
        if      (s == NN * MIN)   x  = (const float*)d_in[i];
        else if (s == NHID * MIN) W1 = (const float*)d_in[i];
        else if (s == MY * NHID)  W2 = (const float*)d_in[i];
        else if (s == 2 * NE)     ei = (const int*)d_in[i];
        else if (s == NHID) {
            if (!b1) b1 = (const float*)d_in[i];
            else     b2 = (const float*)d_in[i];
        }
    }

    __half2* d_h0h = nullptr;
    __half2* d_hA = nullptr;
    __half2* d_hB = nullptr;
    cudaGetSymbolAddress((void**)&d_h0h, g_h0h);
    cudaGetSymbolAddress((void**)&d_hA,  g_hA);
    cudaGetSymbolAddress((void**)&d_hB,  g_hB);

    static cudaStream_t s2 = nullptr;
    static cudaEvent_t evFork = nullptr, evJoin = nullptr;
    if (s2 == nullptr) {
        cudaStreamCreateWithFlags(&s2, cudaStreamNonBlocking);
        cudaEventCreateWithFlags(&evFork, cudaEventDisableTiming);
        cudaEventCreateWithFlags(&evJoin, cudaEventDisableTiming);
    }

    cudaEventRecord(evFork, 0);
    cudaStreamWaitEvent(s2, evFork, 0);

    k_wconv<<<(NHID * MIN + 255) / 256, 256, 0, s2>>>(W1, W2);
    k_mlp_tc<<<(NN + 127) / 128, 256, 0, s2>>>(x, b1, b2);
    cudaEventRecord(evJoin, s2);

    k_degcount4<<<(NE / 4 + 255) / 256, 256>>>(ei);
    k_scan1<<<NBLK, 1024>>>();
    k_scan2<<<1, 128>>>();
    k_scatter<<<(NE + 255) / 256, 256>>>(ei);

    cudaStreamWaitEvent(0, evJoin, 0);

    dim3 pb(32, 2);
    int pg = (NN + 1) / 2;
    k_prop<0><<<pg, pb>>>(d_hA, d_hB, d_h0h, nullptr);
    const __half2* hin = d_hB;
    for (int it = 1; it < 9; it++) {
        __half2* hout = (it & 1) ? d_hA : d_hB;
        k_prop<1><<<pg, pb>>>(hin, hout, d_h0h, nullptr);
        hin = hout;
    }
    k_prop<2><<<pg, pb>>>(hin, nullptr, d_h0h, (float2*)d_out);
}

// round 17
// speedup vs baseline: 1.2961x; 1.0133x over previous
#include <cuda_runtime.h>
#include <cuda_fp16.h>
#include <cstdint>
#include <math.h>

#define NN 100000
#define NE 1600000
#define MY 64
#define MIN 256
#define NHID 64
#define NBLK 98

// ---------------- static scratch ----------------
__device__ __half2 g_h0h[NN * 32];      // teleport term, fp16
__device__ __half2 g_hA[NN * 32];       // ping
__device__ __half2 g_hB[NN * 32];       // pong
__device__ __half  g_w1h[NHID * MIN];   // fp16 W1
__device__ __half  g_w2h[MY * NHID];    // fp16 W2
__device__ int     g_deg[NN];           // degree; self-cleaning (scatter drains to 0)
__device__ float   g_dinv[NN];
__device__ int     g_rowptr[NN + 1];    // BLOCK-LOCAL exclusive scan
__device__ int     g_boff[NBLK + 1];    // block offsets (global = rowptr + boff[i>>10])
__device__ int     g_bsum[NBLK];
__device__ __align__(16) int2 g_edge[NE + 4];

// ---------------- graph preprocessing ----------------
__global__ void k_degcount4(const int* __restrict__ ei) {
    int e4 = blockIdx.x * blockDim.x + threadIdx.x;
    if (e4 < NE / 4) {
        int4 d = __ldg((const int4*)&ei[NE + e4 * 4]);
        atomicAdd(&g_deg[d.x], 1);
        atomicAdd(&g_deg[d.y], 1);
        atomicAdd(&g_deg[d.z], 1);
        atomicAdd(&g_deg[d.w], 1);
    }
}

__global__ void k_scan1() {
    __shared__ int wsum[32];
    int tid = threadIdx.x;
    int i = blockIdx.x * 1024 + tid;
    int v = (i < NN) ? g_deg[i] : 0;
    if (i < NN) g_dinv[i] = rsqrtf((float)(v + 1));
    int lane = tid & 31;
    int w = tid >> 5;
    int x = v;
    #pragma unroll
    for (int o = 1; o < 32; o <<= 1) {
        int t = __shfl_up_sync(0xFFFFFFFFu, x, o);
        if (lane >= o) x += t;
    }
    if (lane == 31) wsum[w] = x;
    __syncthreads();
    if (w == 0) {
        int s = wsum[lane];
        #pragma unroll
        for (int o = 1; o < 32; o <<= 1) {
            int t = __shfl_up_sync(0xFFFFFFFFu, s, o);
            if (lane >= o) s += t;
        }
        wsum[lane] = s;
    }
    __syncthreads();
    int base = (w > 0) ? wsum[w - 1] : 0;
    if (i <= NN) g_rowptr[i] = base + x - v;
    if (tid == 1023) g_bsum[blockIdx.x] = base + x;
}

__global__ void k_scan2() {
    __shared__ int s[128];
    int tid = threadIdx.x;
    int v = (tid < NBLK) ? g_bsum[tid] : 0;
    s[tid] = v;
    __syncthreads();
    #pragma unroll
    for (int o = 1; o < 128; o <<= 1) {
        int t = (tid >= o) ? s[tid - o] : 0;
        __syncthreads();
        s[tid] += t;
        __syncthreads();
    }
    if (tid < NBLK) g_boff[tid] = s[tid] - v;
    if (tid == NBLK - 1) g_boff[NBLK] = s[tid];
}

__global__ void k_scatter(const int* __restrict__ ei) {
    int e = blockIdx.x * blockDim.x + threadIdx.x;
    if (e < NE) {
        int srcv = ei[e];
        int dstv = ei[NE + e];
        int base = g_rowptr[dstv] + g_boff[dstv >> 10];
        int slot = atomicAdd(&g_deg[dstv], -1) - 1;
        float w = 0.9f * g_dinv[srcv] * g_dinv[dstv];
        g_edge[base + slot] = make_int2(srcv, __float_as_int(w));
    }
}

__global__ void k_wconv(const float* __restrict__ W1, const float* __restrict__ W2) {
    int i = blockIdx.x * 256 + threadIdx.x;
    if (i < NHID * MIN) g_w1h[i] = __float2half_rn(W1[i]);
    if (i < MY * NHID)  g_w2h[i] = __float2half_rn(W2[i]);
}

// ---------------- tensor-core MLP helpers ----------------
__device__ __forceinline__ unsigned smem_u32(const void* p) {
    return (unsigned)__cvta_generic_to_shared(p);
}

__device__ __forceinline__ void ldsm_x4(unsigned& r0, unsigned& r1, unsigned& r2, unsigned& r3,
                                        unsigned addr) {
    asm volatile("ldmatrix.sync.aligned.m8n8.x4.shared.b16 {%0,%1,%2,%3}, [%4];"
                 : "=r"(r0), "=r"(r1), "=r"(r2), "=r"(r3) : "r"(addr));
}

__device__ __forceinline__ void ldsm_x2(unsigned& r0, unsigned& r1, unsigned addr) {
    asm volatile("ldmatrix.sync.aligned.m8n8.x2.shared.b16 {%0,%1}, [%2];"
                 : "=r"(r0), "=r"(r1) : "r"(addr));
}

__device__ __forceinline__ void mma16816(float* d,
                                         unsigned a0, unsigned a1, unsigned a2, unsigned a3,
                                         unsigned b0, unsigned b1) {
    asm volatile("mma.sync.aligned.m16n8k16.row.col.f32.f16.f16.f32 "
                 "{%0,%1,%2,%3}, {%4,%5,%6,%7}, {%8,%9}, {%0,%1,%2,%3};"
                 : "+f"(d[0]), "+f"(d[1]), "+f"(d[2]), "+f"(d[3])
                 : "r"(a0), "r"(a1), "r"(a2), "r"(a3), "r"(b0), "r"(b1));
}

// ---------------- fused 2-layer MLP on tensor cores ----------------
#define XS_STR 72
__global__ void k_mlp_tc(const float* __restrict__ x,
                         const float* __restrict__ b1,
                         const float* __restrict__ b2) {
    __shared__ __align__(16) __half xs[128][XS_STR];
    __shared__ __align__(16) __half hid[128][XS_STR];
    __shared__ __align__(16) __half wbuf[64][XS_STR];

    int t = threadIdx.x;
    int w = t >> 5;
    int lane = t & 31;
    int row0 = blockIdx.x * 128;

    float acc[8][4];
    #pragma unroll
    for (int j = 0; j < 8; j++) {
        acc[j][0] = 0.f; acc[j][1] = 0.f; acc[j][2] = 0.f; acc[j][3] = 0.f;
    }

    int a_r    = 16 * w + (lane & 15);
    int a_koff = (lane < 16) ? 0 : 8;
    int b_r    = lane & 7;
    int b_koff = ((lane >> 3) & 1) ? 8 : 0;

    for (int chunk = 0; chunk < 4; chunk++) {
        int kk = chunk * 64;
        for (int i = t; i < 128 * 16; i += 256) {
            int r = i >> 4;
            int c4 = i & 15;
            int grow = row0 + r;
            float4 v = make_float4(0.f, 0.f, 0.f, 0.f);
            if (grow < NN) v = *(const float4*)&x[(size_t)grow * MIN + kk + c4 * 4];
            __half2 p0 = __floats2half2_rn(v.x, v.y);
            __half2 p1 = __floats2half2_rn(v.z, v.w);
            uint2 st;
            st.x = *(unsigned*)&p0;
            st.y = *(unsigned*)&p1;
            *(uint2*)&xs[r][c4 * 4] = st;
        }
        for (int i = t; i < 64 * 16; i += 256) {
            int r = i >> 4;
            int c4 = i & 15;
            *(uint2*)&wbuf[r][c4 * 4] = *(const uint2*)&g_w1h[r * MIN + kk + c4 * 4];
        }
        __syncthreads();
        #pragma unroll
        for (int ks = 0; ks < 4; ks++) {
            int k0 = ks * 16;
            unsigned a0, a1, a2, a3;
            ldsm_x4(a0, a1, a2, a3, smem_u32(&xs[a_r][k0 + a_koff]));
            #pragma unroll
            for (int j = 0; j < 8; j++) {
                unsigned f0, f1;
                ldsm_x2(f0, f1, smem_u32(&wbuf[8 * j + b_r][k0 + b_koff]));
                mma16816(acc[j], a0, a1, a2, a3, f0, f1);
            }
        }
        __syncthreads();
    }

    int rowA = 16 * w + (lane >> 2);
    int colb = (lane & 3) * 2;
    #pragma unroll
    for (int j = 0; j < 8; j++) {
        int col = 8 * j + colb;
        float bj0 = b1[col];
        float bj1 = b1[col + 1];
        *(__half2*)&hid[rowA][col] =
            __floats2half2_rn(fmaxf(acc[j][0] + bj0, 0.f), fmaxf(acc[j][1] + bj1, 0.f));
        *(__half2*)&hid[rowA + 8][col] =
            __floats2half2_rn(fmaxf(acc[j][2] + bj0, 0.f), fmaxf(acc[j][3] + bj1, 0.f));
    }
    for (int i = t; i < 64 * 16; i += 256) {
        int r = i >> 4;
        int c4 = i & 15;
        *(uint2*)&wbuf[r][c4 * 4] = *(const uint2*)&g_w2h[r * NHID + c4 * 4];
    }
    __syncthreads();

    float acc2[8][4];
    #pragma unroll
    for (int j = 0; j < 8; j++) {
        acc2[j][0] = 0.f; acc2[j][1] = 0.f; acc2[j][2] = 0.f; acc2[j][3] = 0.f;
    }
    #pragma unroll
    for (int ks = 0; ks < 4; ks++) {
        int k0 = ks * 16;
        unsigned a0, a1, a2, a3;
        ldsm_x4(a0, a1, a2, a3, smem_u32(&hid[a_r][k0 + a_koff]));
        #pragma unroll
        for (int j = 0; j < 8; j++) {
            unsigned f0, f1;
            ldsm_x2(f0, f1, smem_u32(&wbuf[8 * j + b_r][k0 + b_koff]));
            mma16816(acc2[j], a0, a1, a2, a3, f0, f1);
        }
    }

    int r0g = row0 + rowA;
    int r1g = r0g + 8;
    #pragma unroll
    for (int j = 0; j < 8; j++) {
        int col = 8 * j + colb;
        float bj0 = b2[col];
        float bj1 = b2[col + 1];
        if (r0g < NN) {
            __half2 h2 = __floats2half2_rn(acc2[j][0] + bj0, acc2[j][1] + bj1);
            g_h0h[r0g * 32 + col / 2] = h2;
            g_hA[r0g * 32 + col / 2]  = h2;
        }
        if (r1g < NN) {
            __half2 h2 = __floats2half2_rn(acc2[j][2] + bj0, acc2[j][3] + bj1);
            g_h0h[r1g * 32 + col / 2] = h2;
            g_hA[r1g * 32 + col / 2]  = h2;
        }
    }
}

// ---------------- APPNP propagation step ----------------
// MODE: 0 = first iter (hin == h0), 1 = middle, 2 = last (fp32 output)
// block = (32 lanes, 4 nodes) — measured optimum
template <int MODE>
__global__ void k_prop(const __half2* __restrict__ hin, __half2* __restrict__ hout,
                       const __half2* __restrict__ h0h, float2* __restrict__ outf) {
    int n = blockIdx.x * 4 + threadIdx.y;
    if (n >= NN) return;
    int lane = threadIdx.x;
    int start = g_rowptr[n]     + g_boff[n >> 10];
    int end   = g_rowptr[n + 1] + g_boff[(n + 1) >> 10];
    float dn = g_dinv[n];
    int idx = n * 32 + lane;
    float2 hv = __half22float2(__ldg(&hin[idx]));
    float sl = 0.9f * dn * dn;
    float ax0, ay0;
    if (MODE == 0) {
        float c = sl + 0.1f;
        ax0 = c * hv.x;
        ay0 = c * hv.y;
    } else {
        float2 t0 = __half22float2(__ldg(&h0h[idx]));
        ax0 = fmaf(sl, hv.x, 0.1f * t0.x);
        ay0 = fmaf(sl, hv.y, 0.1f * t0.y);
    }
    float ax1 = 0.f, ay1 = 0.f, ax2 = 0.f, ay2 = 0.f, ax3 = 0.f, ay3 = 0.f;

    int p = start;
    if ((p & 1) && p < end) {
        int2 e = __ldg(&g_edge[p]);
        float w = __int_as_float(e.y);
        float2 v = __half22float2(__ldg(&hin[e.x * 32 + lane]));
        ax0 = fmaf(w, v.x, ax0); ay0 = fmaf(w, v.y, ay0);
        p++;
    }
    for (; p + 8 <= end; p += 8) {
        int4 e01 = __ldg((const int4*)&g_edge[p]);
        int4 e23 = __ldg((const int4*)&g_edge[p + 2]);
        int4 e45 = __ldg((const int4*)&g_edge[p + 4]);
        int4 e67 = __ldg((const int4*)&g_edge[p + 6]);
        float2 v0 = __half22float2(__ldg(&hin[e01.x * 32 + lane]));
        float2 v1 = __half22float2(__ldg(&hin[e01.z * 32 + lane]));
        float2 v2 = __half22float2(__ldg(&hin[e23.x * 32 + lane]));
        float2 v3 = __half22float2(__ldg(&hin[e23.z * 32 + lane]));
        float2 v4 = __half22float2(__ldg(&hin[e45.x * 32 + lane]));
        float2 v5 = __half22float2(__ldg(&hin[e45.z * 32 + lane]));
        float2 v6 = __half22float2(__ldg(&hin[e67.x * 32 + lane]));
        float2 v7 = __half22float2(__ldg(&hin[e67.z * 32 + lane]));
        float w0 = __int_as_float(e01.y);
        float w1 = __int_as_float(e01.w);
        float w2 = __int_as_float(e23.y);
        float w3 = __int_as_float(e23.w);
        float w4 = __int_as_float(e45.y);
        float w5 = __int_as_float(e45.w);
        float w6 = __int_as_float(e67.y);
        float w7 = __int_as_float(e67.w);
        ax0 = fmaf(w0, v0.x, ax0); ay0 = fmaf(w0, v0.y, ay0);
        ax1 = fmaf(w1, v1.x, ax1); ay1 = fmaf(w1, v1.y, ay1);
        ax2 = fmaf(w2, v2.x, ax2); ay2 = fmaf(w2, v2.y, ay2);
        ax3 = fmaf(w3, v3.x, ax3); ay3 = fmaf(w3, v3.y, ay3);
        ax0 = fmaf(w4, v4.x, ax0); ay0 = fmaf(w4, v4.y, ay0);
        ax1 = fmaf(w5, v5.x, ax1); ay1 = fmaf(w5, v5.y, ay1);
        ax2 = fmaf(w6, v6.x, ax2); ay2 = fmaf(w6, v6.y, ay2);
        ax3 = fmaf(w7, v7.x, ax3); ay3 = fmaf(w7, v7.y, ay3);
    }
    if (p + 4 <= end) {
        int4 e01 = __ldg((const int4*)&g_edge[p]);
        int4 e23 = __ldg((const int4*)&g_edge[p + 2]);
        float2 v0 = __half22float2(__ldg(&hin[e01.x * 32 + lane]));
        float2 v1 = __half22float2(__ldg(&hin[e01.z * 32 + lane]));
        float2 v2 = __half22float2(__ldg(&hin[e23.x * 32 + lane]));
        float2 v3 = __half22float2(__ldg(&hin[e23.z * 32 + lane]));
        float w0 = __int_as_float(e01.y);
        float w1 = __int_as_float(e01.w);
        float w2 = __int_as_float(e23.y);
        float w3 = __int_as_float(e23.w);
        ax0 = fmaf(w0, v0.x, ax0); ay0 = fmaf(w0, v0.y, ay0);
        ax1 = fmaf(w1, v1.x, ax1); ay1 = fmaf(w1, v1.y, ay1);
        ax2 = fmaf(w2, v2.x, ax2); ay2 = fmaf(w2, v2.y, ay2);
        ax3 = fmaf(w3, v3.x, ax3); ay3 = fmaf(w3, v3.y, ay3);
        p += 4;
    }
    if (p + 2 <= end) {
        int4 e01 = __ldg((const int4*)&g_edge[p]);
        float w0 = __int_as_float(e01.y);
        float w1 = __int_as_float(e01.w);
        float2 v0 = __half22float2(__ldg(&hin[e01.x * 32 + lane]));
        float2 v1 = __half22float2(__ldg(&hin[e01.z * 32 + lane]));
        ax1 = fmaf(w0, v0.x, ax1); ay1 = fmaf(w0, v0.y, ay1);
        ax2 = fmaf(w1, v1.x, ax2); ay2 = fmaf(w1, v1.y, ay2);
        p += 2;
    }
    if (p < end) {
        int2 e = __ldg(&g_edge[p]);
        float w = __int_as_float(e.y);
        float2 v = __half22float2(__ldg(&hin[e.x * 32 + lane]));
        ax3 = fmaf(w, v.x, ax3); ay3 = fmaf(w, v.y, ay3);
    }
    float ox = (ax0 + ax1) + (ax2 + ax3);
    float oy = (ay0 + ay1) + (ay2 + ay3);
    if (MODE == 2) {
        float2 o;
        o.x = ox;
        o.y = oy;
        outf[idx] = o;
    } else {
        hout[idx] = __floats2half2_rn(ox, oy);
    }
}

// ---------------- launch ----------------
extern "C" void kernel_launch(void* const* d_in, const int* in_sizes, int n_in,
                              void* d_out, int out_size) {
    const float* x  = nullptr;
    const float* W1 = nullptr;
    const float* b1 = nullptr;
    const float* W2 = nullptr;
    const float* b2 = nullptr;
    const int*   ei = nullptr;
    for (int i = 0; i < n_in; i++) {
        int s = in_sizes[i];
        if      (s == NN * MIN)   x  = (const float*)d_in[i];
        else if (s == NHID * MIN) W1 = (const float*)d_in[i];
        else if (s == MY * NHID)  W2 = (const float*)d_in[i];
        else if (s == 2 * NE)     ei = (const int*)d_in[i];
        else if (s == NHID) {
            if (!b1) b1 = (const float*)d_in[i];
            else     b2 = (const float*)d_in[i];
        }
    }

    __half2* d_h0h = nullptr;
    __half2* d_hA = nullptr;
    __half2* d_hB = nullptr;
    cudaGetSymbolAddress((void**)&d_h0h, g_h0h);
    cudaGetSymbolAddress((void**)&d_hA,  g_hA);
    cudaGetSymbolAddress((void**)&d_hB,  g_hB);

    static cudaStream_t s2 = nullptr;
    static cudaEvent_t evFork = nullptr, evJoin = nullptr;
    if (s2 == nullptr) {
        cudaStreamCreateWithFlags(&s2, cudaStreamNonBlocking);
        cudaEventCreateWithFlags(&evFork, cudaEventDisableTiming);
        cudaEventCreateWithFlags(&evJoin, cudaEventDisableTiming);
    }

    cudaEventRecord(evFork, 0);
    cudaStreamWaitEvent(s2, evFork, 0);

    k_wconv<<<(NHID * MIN + 255) / 256, 256, 0, s2>>>(W1, W2);
    k_mlp_tc<<<(NN + 127) / 128, 256, 0, s2>>>(x, b1, b2);
    cudaEventRecord(evJoin, s2);

    k_degcount4<<<(NE / 4 + 255) / 256, 256>>>(ei);
    k_scan1<<<NBLK, 1024>>>();
    k_scan2<<<1, 128>>>();
    k_scatter<<<(NE + 255) / 256, 256>>>(ei);

    cudaStreamWaitEvent(0, evJoin, 0);

    dim3 pb(32, 4);
    int pg = (NN + 3) / 4;
    k_prop<0><<<pg, pb>>>(d_hA, d_hB, d_h0h, nullptr);
    const __half2* hin = d_hB;
    for (int it = 1; it < 9; it++) {
        __half2* hout = (it & 1) ? d_hA : d_hB;
        k_prop<1><<<pg, pb>>>(hin, hout, d_h0h, nullptr);
        hin = hout;
    }
    k_prop<2><<<pg, pb>>>(hin, nullptr, d_h0h, (float2*)d_out);
}